// round 15
// baseline (speedup 1.0000x reference)
#include <cuda_runtime.h>
#include <cuda_bf16.h>
#include <math.h>
#include <stdint.h>

#define BB 32
#define NN 512
#define NF 128
#define FH 64
#define NH 8
#define NC 16
#define ALPHA 0.2f

// ---------------- scratch (device globals; allocation-free rule) -------------
__device__ float          g_f1[NH*BB*NN];
__device__ float          g_f2[NH*BB*NN];
__device__ unsigned       g_adjb[BB*NN*(NN/32)];    // adjacency bitmask [B][N][16]
__device__ __nv_bfloat16  g_x_hi[BB*NN*NF];         // x split hi [B*N][128]
__device__ __nv_bfloat16  g_x_lo[BB*NN*NF];
__device__ __nv_bfloat16  g_WT_hi[NH*FH*NF];        // W^T split [H][f][k]
__device__ __nv_bfloat16  g_WT_lo[NH*FH*NF];
__device__ __nv_bfloat16  g_hT_hi[NH*BB*FH*NN];     // h^T hi [H*B][f][m]
__device__ __nv_bfloat16  g_hT_lo[NH*BB*FH*NN];     // h^T lo
__device__ float          g_houtp[NH*BB*NN*NC];     // per-head partial hout
__device__ float          g_hout[BB*NN*NC];
__device__ float          g_f1o[BB*NN];
__device__ float          g_f2o[BB*NN];

// ---------------- helpers ----------------------------------------------------
__device__ __forceinline__ uint32_t smem_u32(const void* p) {
    uint32_t a;
    asm("{ .reg .u64 t; cvta.to.shared.u64 t, %1; cvt.u32.u64 %0, t; }"
        : "=r"(a) : "l"(p));
    return a;
}
#define SWZ(o) ((o) ^ ((((unsigned)(o)) >> 3) & 0x70))
#define ONES2 0x3F803F80u   // bf16x2 {1.0, 1.0}

// truncation split: hi = top-16 bits (exact via PRMT), lo = v - hi (rn bf16x2)
__device__ __forceinline__ void split2t(float v0, float v1, unsigned& hw, unsigned& lw) {
    unsigned b0 = __float_as_uint(v0), b1 = __float_as_uint(v1);
    hw = __byte_perm(b0, b1, 0x7632);
    float l0 = v0 - __uint_as_float(b0 & 0xffff0000u);
    float l1 = v1 - __uint_as_float(b1 & 0xffff0000u);
    asm("cvt.rn.bf16x2.f32 %0, %1, %2;" : "=r"(lw) : "f"(l1), "f"(l0));
}

#define LDSM_X4(r0, r1, r2, r3, addr) \
    asm volatile("ldmatrix.sync.aligned.m8n8.x4.shared.b16 {%0,%1,%2,%3}, [%4];" \
        : "=r"(r0), "=r"(r1), "=r"(r2), "=r"(r3) : "r"(addr))

#define MMA16816(c, a0, a1, a2, a3, b0, b1) \
    asm volatile("mma.sync.aligned.m16n8k16.row.col.f32.bf16.bf16.f32 " \
        "{%0,%1,%2,%3}, {%4,%5,%6,%7}, {%8,%9}, {%0,%1,%2,%3};" \
        : "+f"((c)[0]), "+f"((c)[1]), "+f"((c)[2]), "+f"((c)[3]) \
        : "r"(a0), "r"(a1), "r"(a2), "r"(a3), "r"(b0), "r"(b1))

// ---------------- 1) pack adjacency to bits ---------------------------------
__global__ void k_pack_adj(const int* __restrict__ adj) {
    int gw   = blockIdx.x * 8 + (threadIdx.x >> 5);
    int lane = threadIdx.x & 31;
    int m  = ((gw & 15) << 5) | lane;
    int bn = gw >> 4;
    int v  = adj[bn * NN + m] > 0;
    unsigned msk = __ballot_sync(0xffffffffu, v);
    if (lane == 0) g_adjb[gw] = msk;
}

// ---------------- 1b) split x and W^T into bf16 hi/lo (truncation) ----------
__global__ void k_prep(const float* __restrict__ x, const float* __restrict__ W) {
    int tid = threadIdx.x;
    if (blockIdx.x < 2048) {
        int gid = blockIdx.x * 256 + tid;
        float4 v = ((const float4*)x)[gid];
        unsigned h0, l0, h1, l1;
        split2t(v.x, v.y, h0, l0);
        split2t(v.z, v.w, h1, l1);
        ((uint2*)g_x_hi)[gid] = make_uint2(h0, h1);
        ((uint2*)g_x_lo)[gid] = make_uint2(l0, l1);
    } else {
        int gid = (blockIdx.x - 2048) * 256 + tid;
        int idx = gid * 4;
        int h = idx >> 13, rem = idx & 8191;
        int f = rem >> 7, k0 = rem & 127;
        const float* wp = W + h * NF * FH + f;
        float v0 = wp[(k0 + 0) * FH], v1 = wp[(k0 + 1) * FH];
        float v2 = wp[(k0 + 2) * FH], v3 = wp[(k0 + 3) * FH];
        unsigned h0, l0, h1, l1;
        split2t(v0, v1, h0, l0);
        split2t(v2, v3, h1, l1);
        ((uint2*)g_WT_hi)[gid] = make_uint2(h0, h1);
        ((uint2*)g_WT_lo)[gid] = make_uint2(l0, l1);
    }
}

// ---------------- 2) h = x @ W per head via HMMA bf16x3 + epilogue ----------
// (R12 per-head grid restored; epilogue uses truncation split.)
#define HG_XH 0
#define HG_XL 16384
#define HG_WH 32768
#define HG_WL 49152
#define SMEM_HG 65536

__global__ __launch_bounds__(128) void k_head_gemm(const float* __restrict__ a1h,
                                                   const float* __restrict__ a2h) {
    extern __shared__ char sm[];
    uint32_t smb = smem_u32(sm);
    int head = blockIdx.z, b = blockIdx.y, n0 = blockIdx.x * 64;
    int hb = head * BB + b;
    int tid = threadIdx.x, warp = tid >> 5, lane = tid & 31;

    {
        const uint4* xh4 = (const uint4*)g_x_hi + (size_t)(b * NN + n0) * 16;
        const uint4* xl4 = (const uint4*)g_x_lo + (size_t)(b * NN + n0) * 16;
        const uint4* wh4 = (const uint4*)g_WT_hi + (size_t)head * FH * 16;
        const uint4* wl4 = (const uint4*)g_WT_lo + (size_t)head * FH * 16;
        #pragma unroll
        for (int i = 0; i < 8; i++) {
            int idx = tid + i * 128;
            int row = idx >> 4, kq = idx & 15;
            uint32_t off = (kq >> 3) * 8192 + SWZ(row * 128 + (kq & 7) * 16);
            *(uint4*)(sm + HG_XH + off) = xh4[idx];
            *(uint4*)(sm + HG_XL + off) = xl4[idx];
            *(uint4*)(sm + HG_WH + off) = wh4[idx];
            *(uint4*)(sm + HG_WL + off) = wl4[idx];
        }
    }
    __syncthreads();

    int q = lane >> 3, ri = lane & 7;
    int arow = warp * 16 + ((q & 1) << 3) + ri;
    int frow = ((q & 1) << 3) + ri;
    int akb  = (q >> 1) << 4;

    float c[8][4];
    #pragma unroll
    for (int i = 0; i < 8; i++)
        #pragma unroll
        for (int j = 0; j < 4; j++) c[i][j] = 0.f;

    #pragma unroll
    for (int kc = 0; kc < 8; kc++) {
        uint32_t ao = (kc >> 2) * 8192 + SWZ(arow * 128 + (kc & 3) * 32 + akb);
        uint32_t ah[4], al[4];
        LDSM_X4(ah[0], ah[1], ah[2], ah[3], smb + HG_XH + ao);
        LDSM_X4(al[0], al[1], al[2], al[3], smb + HG_XL + ao);
        #pragma unroll
        for (int np = 0; np < 4; np++) {
            uint32_t bo = (kc >> 2) * 8192 + SWZ((np * 16 + frow) * 128 + (kc & 3) * 32 + akb);
            uint32_t bh[4], bl[4];
            LDSM_X4(bh[0], bh[1], bh[2], bh[3], smb + HG_WH + bo);
            LDSM_X4(bl[0], bl[1], bl[2], bl[3], smb + HG_WL + bo);
            MMA16816(c[np*2],   ah[0], ah[1], ah[2], ah[3], bh[0], bh[2]);
            MMA16816(c[np*2],   ah[0], ah[1], ah[2], ah[3], bl[0], bl[2]);
            MMA16816(c[np*2],   al[0], al[1], al[2], al[3], bh[0], bh[2]);
            MMA16816(c[np*2+1], ah[0], ah[1], ah[2], ah[3], bh[1], bh[3]);
            MMA16816(c[np*2+1], ah[0], ah[1], ah[2], ah[3], bl[1], bl[3]);
            MMA16816(c[np*2+1], al[0], al[1], al[2], al[3], bh[1], bh[3]);
        }
    }

    __syncthreads();
    float* hstage = (float*)sm;
    int g4 = lane >> 2, t4 = lane & 3;
    int row0 = warp * 16 + g4;
    #pragma unroll
    for (int np = 0; np < 8; np++) {
        int col = np * 8 + t4 * 2;
        hstage[row0 * 65 + col]       = c[np][0];
        hstage[row0 * 65 + col + 1]   = c[np][1];
        hstage[(row0+8) * 65 + col]   = c[np][2];
        hstage[(row0+8) * 65 + col+1] = c[np][3];
    }
    __syncthreads();

    {
        int r = tid >> 1, half = tid & 1;
        float s1 = 0.f, s2 = 0.f;
        #pragma unroll
        for (int k2 = 0; k2 < 32; k2++) {
            int f = half * 32 + k2;
            float v = hstage[r * 65 + f];
            s1 = fmaf(v, a1h[head * FH + f], s1);
            s2 = fmaf(v, a2h[head * FH + f], s2);
        }
        s1 += __shfl_xor_sync(0xffffffffu, s1, 1);
        s2 += __shfl_xor_sync(0xffffffffu, s2, 1);
        if (half == 0) { g_f1[hb * NN + n0 + r] = s1; g_f2[hb * NN + n0 + r] = s2; }
    }
    {
        int f = tid >> 1, nh2 = tid & 1;
        unsigned hw[16], lw[16];
        #pragma unroll
        for (int k2 = 0; k2 < 16; k2++) {
            float v0 = hstage[(nh2 * 32 + 2 * k2)     * 65 + f];
            float v1 = hstage[(nh2 * 32 + 2 * k2 + 1) * 65 + f];
            split2t(v0, v1, hw[k2], lw[k2]);
        }
        size_t base = ((size_t)(hb * FH + f)) * NN + n0 + nh2 * 32;
        #pragma unroll
        for (int i = 0; i < 4; i++) {
            *(uint4*)(g_hT_hi + base + i * 8) = make_uint4(hw[i*4], hw[i*4+1], hw[i*4+2], hw[i*4+3]);
            *(uint4*)(g_hT_lo + base + i * 8) = make_uint4(lw[i*4], lw[i*4+1], lw[i*4+2], lw[i*4+3]);
        }
    }
}

// ---------------- 3) tensor-core fused attention (mma.sync bf16x3) ----------
// Double-buffered chunk pipeline: MMA(buf j) overlaps production(buf j^1),
// one sync per chunk. exp(leaky(z)) = max(e^z, e^{.2z}) (exp monotone).
// B-tile global loads prefetched into registers before the ALU phase.
#define BUF_SZ    49152      // P_HI 16K + P_LO 16K + BH 8K + BL 8K
#define P_HI_R    0
#define P_LO_R    16384
#define BH_R      32768
#define BL_R      40960
#define F2P_OFF   98304      // 512 float2 = 4KB
#define SMEM_ATTN 102400
#define WOUT_OFF  34048      // epilogue Wout slice (buffer region dead)

__global__ __launch_bounds__(256, 2) void k_attn(const float* __restrict__ Wout) {
    extern __shared__ char sm[];
    uint32_t smb = smem_u32(sm);
    float2* f2p = (float2*)(sm + F2P_OFF);
    int head = blockIdx.z, b = blockIdx.y, n0 = blockIdx.x * 128;
    int hb = head * BB + b;
    int tid = threadIdx.x, warp = tid >> 5, lane = tid & 31;

    // factorized-exp tables
    #pragma unroll
    for (int i = 0; i < 2; i++) {
        int m = tid + i * 256;
        float f2v = g_f2[hb * NN + m];
        f2p[m] = make_float2(__expf(f2v), __expf(ALPHA * f2v));
    }
    int r = tid >> 1, half = tid & 1;
    float f1v = g_f1[hb * NN + n0 + r];
    float Ae = __expf(f1v), A2e = __expf(ALPHA * f1v);
    const unsigned* gadj_row = g_adjb + (size_t)(b * NN + n0 + r) * 16;

    float c[8][4];
    #pragma unroll
    for (int i = 0; i < 8; i++)
        #pragma unroll
        for (int j = 0; j < 4; j++) c[i][j] = 0.f;
    float c2[4] = {0.f, 0.f, 0.f, 0.f};     // ones-MMA row sums

    int q = lane >> 3, ri = lane & 7;
    int arow = warp * 16 + ((q & 1) << 3) + ri;
    int frow = ((q & 1) << 3) + ri;
    int akb  = (q >> 1) << 4;

    // hoisted LDSM addresses (buffer-relative)
    uint32_t aoff[4], boff[4][4];
    #pragma unroll
    for (int kc = 0; kc < 4; kc++) {
        aoff[kc] = SWZ(arow * 128 + kc * 32 + akb);
        #pragma unroll
        for (int np = 0; np < 4; np++)
            boff[np][kc] = SWZ((np * 16 + frow) * 128 + kc * 32 + akb);
    }

    const uint4* shp = (const uint4*)g_hT_hi + (size_t)hb * FH * (NN / 8);
    const uint4* slp = (const uint4*)g_hT_lo + (size_t)hb * FH * (NN / 8);

    // hoisted B-load geometry
    int bf = tid >> 3, bj = tid & 7;
    uint32_t bso  = SWZ(bf * 128 + bj * 16);
    uint32_t bso1 = SWZ((bf + 32) * 128 + bj * 16);
    int bgi0 = bf * 64 + bj, bgi1 = (bf + 32) * 64 + bj;

    #define PRODUCE(chv, bufbase) { \
        uint4 pfA = shp[bgi0 + (chv) * 8]; \
        uint4 pfB = shp[bgi1 + (chv) * 8]; \
        uint4 pfC = slp[bgi0 + (chv) * 8]; \
        uint4 pfD = slp[bgi1 + (chv) * 8]; \
        unsigned word = gadj_row[(chv) * 2 + half]; \
        const float4* bp4 = (const float4*)(f2p + (chv) * 64 + half * 32); \
        char* Ph = sm + (bufbase) + P_HI_R; \
        char* Pl = sm + (bufbase) + P_LO_R; \
        _Pragma("unroll") \
        for (int g = 0; g < 4; g++) { \
            unsigned hh[4], ll[4]; \
            _Pragma("unroll") \
            for (int pj = 0; pj < 4; pj++) { \
                float4 B2 = bp4[g * 4 + pj]; \
                int k0 = g * 8 + pj * 2; \
                float v0 = fmaxf(Ae * B2.x, A2e * B2.y); \
                float v1 = fmaxf(Ae * B2.z, A2e * B2.w); \
                v0 = ((word >> k0) & 1u) ? v0 : 0.f; \
                v1 = ((word >> (k0 + 1)) & 1u) ? v1 : 0.f; \
                split2t(v0, v1, hh[pj], ll[pj]); \
            } \
            uint32_t off = SWZ(r * 128 + half * 64 + g * 16); \
            *(uint4*)(Ph + off) = make_uint4(hh[0], hh[1], hh[2], hh[3]); \
            *(uint4*)(Pl + off) = make_uint4(ll[0], ll[1], ll[2], ll[3]); \
        } \
        *(uint4*)(sm + (bufbase) + BH_R + bso)  = pfA; \
        *(uint4*)(sm + (bufbase) + BH_R + bso1) = pfB; \
        *(uint4*)(sm + (bufbase) + BL_R + bso)  = pfC; \
        *(uint4*)(sm + (bufbase) + BL_R + bso1) = pfD; \
    }

    // f2p table must be visible to ALL threads before any production reads it
    __syncthreads();
    PRODUCE(0, 0)
    __syncthreads();

    for (int ch = 0; ch < 8; ch++) {
        uint32_t bufb = (ch & 1) * BUF_SZ;
        // ---- HMMA from buffer j ----
        #pragma unroll
        for (int kc = 0; kc < 4; kc++) {
            uint32_t ah[4], al[4];
            LDSM_X4(ah[0], ah[1], ah[2], ah[3], smb + bufb + P_HI_R + aoff[kc]);
            LDSM_X4(al[0], al[1], al[2], al[3], smb + bufb + P_LO_R + aoff[kc]);
            MMA16816(c2, ah[0], ah[1], ah[2], ah[3], ONES2, ONES2);
            MMA16816(c2, al[0], al[1], al[2], al[3], ONES2, ONES2);
            #pragma unroll
            for (int np = 0; np < 4; np++) {
                uint32_t bh[4], bl[4];
                LDSM_X4(bh[0], bh[1], bh[2], bh[3], smb + bufb + BH_R + boff[np][kc]);
                LDSM_X4(bl[0], bl[1], bl[2], bl[3], smb + bufb + BL_R + boff[np][kc]);
                MMA16816(c[np*2],   ah[0], ah[1], ah[2], ah[3], bh[0], bh[2]);
                MMA16816(c[np*2],   ah[0], ah[1], ah[2], ah[3], bl[0], bl[2]);
                MMA16816(c[np*2],   al[0], al[1], al[2], al[3], bh[0], bh[2]);
                MMA16816(c[np*2+1], ah[0], ah[1], ah[2], ah[3], bh[1], bh[3]);
                MMA16816(c[np*2+1], ah[0], ah[1], ah[2], ah[3], bl[1], bl[3]);
                MMA16816(c[np*2+1], al[0], al[1], al[2], al[3], bh[1], bh[3]);
            }
        }
        // ---- produce next chunk into the other buffer ----
        if (ch < 7) PRODUCE(ch + 1, (uint32_t)(((ch + 1) & 1) * BUF_SZ))
        __syncthreads();
    }

    // rinv straight from ones-MMA accumulators
    float rinv0 = 1.0f / c2[0];
    float rinv1 = 1.0f / c2[2];

    // ---- stage elu(h'/s) [128][65] fp32 + load Wout slice ----
    float* hstage = (float*)sm;
    float* swout  = (float*)(sm + WOUT_OFF);
    ((float4*)swout)[tid] = ((const float4*)Wout)[head * 256 + tid];
    int g4 = lane >> 2, t4 = lane & 3;
    int row0 = warp * 16 + g4;
    #pragma unroll
    for (int np = 0; np < 8; np++) {
        int col = np * 8 + t4 * 2;
        float u0 = c[np][0] * rinv0, u1 = c[np][1] * rinv0;
        float v0 = c[np][2] * rinv1, v1 = c[np][3] * rinv1;
        u0 = u0 > 0.f ? u0 : expm1f(u0);
        u1 = u1 > 0.f ? u1 : expm1f(u1);
        v0 = v0 > 0.f ? v0 : expm1f(v0);
        v1 = v1 > 0.f ? v1 : expm1f(v1);
        hstage[row0 * 65 + col]         = u0;
        hstage[row0 * 65 + col + 1]     = u1;
        hstage[(row0 + 8) * 65 + col]   = v0;
        hstage[(row0 + 8) * 65 + col+1] = v1;
    }
    __syncthreads();

    // ---- partial hout ----
    {
        int row = tid >> 1, chf = tid & 1;
        float acc[8] = {};
        #pragma unroll 8
        for (int k = 0; k < 64; k++) {
            float a = hstage[row * 65 + k];
            const float* wr = swout + k * 16 + chf * 8;
            #pragma unroll
            for (int j = 0; j < 8; j++) acc[j] = fmaf(a, wr[j], acc[j]);
        }
        float* op = g_houtp + ((size_t)head * BB * NN + b * NN + n0 + row) * NC + chf * 8;
        *(float4*)op       = make_float4(acc[0], acc[1], acc[2], acc[3]);
        *(float4*)(op + 4) = make_float4(acc[4], acc[5], acc[6], acc[7]);
    }
}

// ---------------- 4) combine partial hout + f1o/f2o -------------------------
__global__ __launch_bounds__(256) void k_combine(const float* __restrict__ a1o,
                                                 const float* __restrict__ a2o) {
    int bn = blockIdx.x * 256 + threadIdx.x;
    float acc[16] = {};
    #pragma unroll
    for (int h = 0; h < NH; h++) {
        const float4* p = (const float4*)(g_houtp + ((size_t)h * BB * NN + bn) * NC);
        #pragma unroll
        for (int i = 0; i < 4; i++) {
            float4 v = p[i];
            acc[i*4]   += v.x; acc[i*4+1] += v.y;
            acc[i*4+2] += v.z; acc[i*4+3] += v.w;
        }
    }
    float4* op = (float4*)(g_hout + (size_t)bn * NC);
    #pragma unroll
    for (int i = 0; i < 4; i++)
        op[i] = make_float4(acc[i*4], acc[i*4+1], acc[i*4+2], acc[i*4+3]);
    float s1 = 0.f, s2 = 0.f;
    #pragma unroll
    for (int c = 0; c < 16; c++) { s1 = fmaf(acc[c], a1o[c], s1); s2 = fmaf(acc[c], a2o[c], s2); }
    g_f1o[bn] = s1; g_f2o[bn] = s2;
}

// ---------------- 5) output attention (F=16, max-factorized exp) ------------
__global__ __launch_bounds__(256) void k_attn_out(float* __restrict__ out) {
    int b = blockIdx.y, n0 = blockIdx.x * 64;
    __shared__ float2   f2p[NN];        // 4KB
    __shared__ unsigned adjw[64 * 16];  // 4KB
    __shared__ float    hs[64 * 16];    // 4KB
    __shared__ float    ps[64 * 68];    // 17.4KB
    int tid = threadIdx.x;

    #pragma unroll
    for (int i = 0; i < 2; i++) {
        int m = tid + i * 256;
        float f2v = g_f2o[b * NN + m];
        f2p[m] = make_float2(__expf(f2v), __expf(ALPHA * f2v));
    }
    {
        const unsigned* ab = g_adjb + (size_t)(b * NN + n0) * 16;
        for (int i = tid; i < 1024; i += 256) adjw[i] = ab[i];
    }
    int r = tid >> 2, q = tid & 3;
    float f1v = g_f1o[b * NN + n0 + r];
    float Ae = __expf(f1v), A2e = __expf(ALPHA * f1v);

    float s = 0.f;
    float4 acc = {0, 0, 0, 0};
    const float4* hg4 = (const float4*)g_hout + (size_t)b * NN * 4;
    for (int c = 0; c < 8; c++) {
        __syncthreads();
        ((float4*)hs)[tid] = hg4[c * 256 + tid];
        {
            unsigned word = adjw[(r << 4) + c * 2 + (q >> 1)];
            int sb = (q & 1) * 16;
            const float2* bp = f2p + c * 64 + q * 16;
            #pragma unroll
            for (int t = 0; t < 16; t++) {
                float2 Bv = bp[t];
                float val = fmaxf(Ae * Bv.x, A2e * Bv.y);
                val = ((word >> (sb + t)) & 1u) ? val : 0.f;
                ps[r * 68 + q * 16 + t] = val;
            }
        }
        __syncthreads();
        #pragma unroll 8
        for (int mm = 0; mm < 64; mm++) {
            float p = ps[r * 68 + mm];
            s += p;
            float4 hv = ((const float4*)hs)[mm * 4 + q];
            acc.x = fmaf(p, hv.x, acc.x); acc.y = fmaf(p, hv.y, acc.y);
            acc.z = fmaf(p, hv.z, acc.z); acc.w = fmaf(p, hv.w, acc.w);
        }
    }
    float rinv = 1.0f / s;
    acc.x *= rinv; acc.y *= rinv; acc.z *= rinv; acc.w *= rinv;
    *(float4*)&out[(size_t)(b * NN + n0 + r) * NC + (q << 2)] = acc;
}

// ---------------- launch ----------------------------------------------------
extern "C" void kernel_launch(void* const* d_in, const int* in_sizes, int n_in,
                              void* d_out, int out_size) {
    const float* x   = (const float*)d_in[0];
    const int*   adj = (const int*)  d_in[1];
    const float* Wh  = (const float*)d_in[2];
    const float* a1h = (const float*)d_in[3];
    const float* a2h = (const float*)d_in[4];
    const float* Wo  = (const float*)d_in[5];
    const float* a1o = (const float*)d_in[6];
    const float* a2o = (const float*)d_in[7];
    float* out = (float*)d_out;

    cudaFuncSetAttribute(k_head_gemm, cudaFuncAttributeMaxDynamicSharedMemorySize, SMEM_HG);
    cudaFuncSetAttribute(k_attn, cudaFuncAttributeMaxDynamicSharedMemorySize, SMEM_ATTN);

    k_pack_adj <<<BB * NN * 16 / 8, 256>>>(adj);
    k_prep     <<<2112, 256>>>(x, Wh);
    k_head_gemm<<<dim3(8, BB, NH), 128, SMEM_HG>>>(a1h, a2h);
    k_attn     <<<dim3(4, BB, NH), 256, SMEM_ATTN>>>(Wo);
    k_combine  <<<BB * NN / 256, 256>>>(a1o, a2o);
    k_attn_out <<<dim3(8, BB), 256>>>(out);
}

// round 17
// speedup vs baseline: 1.0305x; 1.0305x over previous
#include <cuda_runtime.h>
#include <cuda_bf16.h>
#include <math.h>
#include <stdint.h>

#define BB 32
#define NN 512
#define NF 128
#define FH 64
#define NH 8
#define NC 16
#define ALPHA 0.2f

// ---------------- scratch (device globals; allocation-free rule) -------------
__device__ float          g_f1[NH*BB*NN];
__device__ float          g_f2[NH*BB*NN];
__device__ unsigned       g_adjb[BB*NN*(NN/32)];    // adjacency bitmask [B][N][16]
__device__ __nv_bfloat16  g_x_hi[BB*NN*NF];         // x split hi [B*N][128]
__device__ __nv_bfloat16  g_x_lo[BB*NN*NF];
__device__ __nv_bfloat16  g_WT_hi[NH*FH*NF];        // W^T split [H][f][k]
__device__ __nv_bfloat16  g_WT_lo[NH*FH*NF];
__device__ __nv_bfloat16  g_hT_hi[NH*BB*FH*NN];     // h^T hi [H*B][f][m]
__device__ __nv_bfloat16  g_hT_lo[NH*BB*FH*NN];     // h^T lo
__device__ float          g_houtp[NH*BB*NN*NC];     // per-head partial hout
__device__ float          g_hout[BB*NN*NC];
__device__ float          g_f1o[BB*NN];
__device__ float          g_f2o[BB*NN];

// ---------------- helpers ----------------------------------------------------
__device__ __forceinline__ uint32_t smem_u32(const void* p) {
    uint32_t a;
    asm("{ .reg .u64 t; cvta.to.shared.u64 t, %1; cvt.u32.u64 %0, t; }"
        : "=r"(a) : "l"(p));
    return a;
}
#define SWZ(o) ((o) ^ ((((unsigned)(o)) >> 3) & 0x70))
#define ONES2 0x3F803F80u   // bf16x2 {1.0, 1.0}

__device__ __forceinline__ unsigned packbf2(__nv_bfloat16 a, __nv_bfloat16 b) {
    __nv_bfloat162 p; p.x = a; p.y = b;
    return *(unsigned*)&p;
}
// rounding split (prep / head_gemm epilogue)
__device__ __forceinline__ void split2(float v0, float v1, unsigned& hw, unsigned& lw) {
    __nv_bfloat16 h0 = __float2bfloat16(v0), h1 = __float2bfloat16(v1);
    __nv_bfloat16 l0 = __float2bfloat16(v0 - __bfloat162float(h0));
    __nv_bfloat16 l1 = __float2bfloat16(v1 - __bfloat162float(h1));
    hw = packbf2(h0, h1);
    lw = packbf2(l0, l1);
}
// truncation split: hi = top-16 bits (exact via PRMT), lo = v - hi (rn bf16x2)
__device__ __forceinline__ void split2t(float v0, float v1, unsigned& hw, unsigned& lw) {
    unsigned b0 = __float_as_uint(v0), b1 = __float_as_uint(v1);
    hw = __byte_perm(b0, b1, 0x7632);
    float l0 = v0 - __uint_as_float(b0 & 0xffff0000u);
    float l1 = v1 - __uint_as_float(b1 & 0xffff0000u);
    asm("cvt.rn.bf16x2.f32 %0, %1, %2;" : "=r"(lw) : "f"(l1), "f"(l0));
}

#define LDSM_X4(r0, r1, r2, r3, addr) \
    asm volatile("ldmatrix.sync.aligned.m8n8.x4.shared.b16 {%0,%1,%2,%3}, [%4];" \
        : "=r"(r0), "=r"(r1), "=r"(r2), "=r"(r3) : "r"(addr))

#define MMA16816(c, a0, a1, a2, a3, b0, b1) \
    asm volatile("mma.sync.aligned.m16n8k16.row.col.f32.bf16.bf16.f32 " \
        "{%0,%1,%2,%3}, {%4,%5,%6,%7}, {%8,%9}, {%0,%1,%2,%3};" \
        : "+f"((c)[0]), "+f"((c)[1]), "+f"((c)[2]), "+f"((c)[3]) \
        : "r"(a0), "r"(a1), "r"(a2), "r"(a3), "r"(b0), "r"(b1))

// ---------------- 1) pack adjacency to bits ---------------------------------
__global__ void k_pack_adj(const int* __restrict__ adj) {
    int gw   = blockIdx.x * 8 + (threadIdx.x >> 5);
    int lane = threadIdx.x & 31;
    int m  = ((gw & 15) << 5) | lane;
    int bn = gw >> 4;
    int v  = adj[bn * NN + m] > 0;
    unsigned msk = __ballot_sync(0xffffffffu, v);
    if (lane == 0) g_adjb[gw] = msk;
}

// ---------------- 1b) split x and W^T into bf16 hi/lo -----------------------
__global__ void k_prep(const float* __restrict__ x, const float* __restrict__ W) {
    int tid = threadIdx.x;
    if (blockIdx.x < 2048) {
        int gid = blockIdx.x * 256 + tid;
        float4 v = ((const float4*)x)[gid];
        unsigned h0, l0, h1, l1;
        split2(v.x, v.y, h0, l0);
        split2(v.z, v.w, h1, l1);
        ((uint2*)g_x_hi)[gid] = make_uint2(h0, h1);
        ((uint2*)g_x_lo)[gid] = make_uint2(l0, l1);
    } else {
        int gid = (blockIdx.x - 2048) * 256 + tid;
        int idx = gid * 4;
        int h = idx >> 13, rem = idx & 8191;
        int f = rem >> 7, k0 = rem & 127;
        const float* wp = W + h * NF * FH + f;
        float v0 = wp[(k0 + 0) * FH], v1 = wp[(k0 + 1) * FH];
        float v2 = wp[(k0 + 2) * FH], v3 = wp[(k0 + 3) * FH];
        unsigned h0, l0, h1, l1;
        split2(v0, v1, h0, l0);
        split2(v2, v3, h1, l1);
        ((uint2*)g_WT_hi)[gid] = make_uint2(h0, h1);
        ((uint2*)g_WT_lo)[gid] = make_uint2(l0, l1);
    }
}

// ---------------- 2) h = x @ W per head via HMMA bf16x3 + epilogue ----------
#define HG_XH 0
#define HG_XL 16384
#define HG_WH 32768
#define HG_WL 49152
#define SMEM_HG 65536

__global__ __launch_bounds__(128) void k_head_gemm(const float* __restrict__ a1h,
                                                   const float* __restrict__ a2h) {
    extern __shared__ char sm[];
    uint32_t smb = smem_u32(sm);
    int head = blockIdx.z, b = blockIdx.y, n0 = blockIdx.x * 64;
    int hb = head * BB + b;
    int tid = threadIdx.x, warp = tid >> 5, lane = tid & 31;

    {
        const uint4* xh4 = (const uint4*)g_x_hi + (size_t)(b * NN + n0) * 16;
        const uint4* xl4 = (const uint4*)g_x_lo + (size_t)(b * NN + n0) * 16;
        const uint4* wh4 = (const uint4*)g_WT_hi + (size_t)head * FH * 16;
        const uint4* wl4 = (const uint4*)g_WT_lo + (size_t)head * FH * 16;
        #pragma unroll
        for (int i = 0; i < 8; i++) {
            int idx = tid + i * 128;
            int row = idx >> 4, kq = idx & 15;
            uint32_t off = (kq >> 3) * 8192 + SWZ(row * 128 + (kq & 7) * 16);
            *(uint4*)(sm + HG_XH + off) = xh4[idx];
            *(uint4*)(sm + HG_XL + off) = xl4[idx];
            *(uint4*)(sm + HG_WH + off) = wh4[idx];
            *(uint4*)(sm + HG_WL + off) = wl4[idx];
        }
    }
    __syncthreads();

    int q = lane >> 3, ri = lane & 7;
    int arow = warp * 16 + ((q & 1) << 3) + ri;
    int frow = ((q & 1) << 3) + ri;
    int akb  = (q >> 1) << 4;

    float c[8][4];
    #pragma unroll
    for (int i = 0; i < 8; i++)
        #pragma unroll
        for (int j = 0; j < 4; j++) c[i][j] = 0.f;

    #pragma unroll
    for (int kc = 0; kc < 8; kc++) {
        uint32_t ao = (kc >> 2) * 8192 + SWZ(arow * 128 + (kc & 3) * 32 + akb);
        uint32_t ah[4], al[4];
        LDSM_X4(ah[0], ah[1], ah[2], ah[3], smb + HG_XH + ao);
        LDSM_X4(al[0], al[1], al[2], al[3], smb + HG_XL + ao);
        #pragma unroll
        for (int np = 0; np < 4; np++) {
            uint32_t bo = (kc >> 2) * 8192 + SWZ((np * 16 + frow) * 128 + (kc & 3) * 32 + akb);
            uint32_t bh[4], bl[4];
            LDSM_X4(bh[0], bh[1], bh[2], bh[3], smb + HG_WH + bo);
            LDSM_X4(bl[0], bl[1], bl[2], bl[3], smb + HG_WL + bo);
            MMA16816(c[np*2],   ah[0], ah[1], ah[2], ah[3], bh[0], bh[2]);
            MMA16816(c[np*2],   ah[0], ah[1], ah[2], ah[3], bl[0], bl[2]);
            MMA16816(c[np*2],   al[0], al[1], al[2], al[3], bh[0], bh[2]);
            MMA16816(c[np*2+1], ah[0], ah[1], ah[2], ah[3], bh[1], bh[3]);
            MMA16816(c[np*2+1], ah[0], ah[1], ah[2], ah[3], bl[1], bl[3]);
            MMA16816(c[np*2+1], al[0], al[1], al[2], al[3], bh[1], bh[3]);
        }
    }

    __syncthreads();
    float* hstage = (float*)sm;
    int g4 = lane >> 2, t4 = lane & 3;
    int row0 = warp * 16 + g4;
    #pragma unroll
    for (int np = 0; np < 8; np++) {
        int col = np * 8 + t4 * 2;
        hstage[row0 * 65 + col]       = c[np][0];
        hstage[row0 * 65 + col + 1]   = c[np][1];
        hstage[(row0+8) * 65 + col]   = c[np][2];
        hstage[(row0+8) * 65 + col+1] = c[np][3];
    }
    __syncthreads();

    {
        int r = tid >> 1, half = tid & 1;
        float s1 = 0.f, s2 = 0.f;
        #pragma unroll
        for (int k2 = 0; k2 < 32; k2++) {
            int f = half * 32 + k2;
            float v = hstage[r * 65 + f];
            s1 = fmaf(v, a1h[head * FH + f], s1);
            s2 = fmaf(v, a2h[head * FH + f], s2);
        }
        s1 += __shfl_xor_sync(0xffffffffu, s1, 1);
        s2 += __shfl_xor_sync(0xffffffffu, s2, 1);
        if (half == 0) { g_f1[hb * NN + n0 + r] = s1; g_f2[hb * NN + n0 + r] = s2; }
    }
    {
        int f = tid >> 1, nh2 = tid & 1;
        unsigned hw[16], lw[16];
        #pragma unroll
        for (int k2 = 0; k2 < 16; k2++) {
            float v0 = hstage[(nh2 * 32 + 2 * k2)     * 65 + f];
            float v1 = hstage[(nh2 * 32 + 2 * k2 + 1) * 65 + f];
            split2(v0, v1, hw[k2], lw[k2]);
        }
        size_t base = ((size_t)(hb * FH + f)) * NN + n0 + nh2 * 32;
        #pragma unroll
        for (int i = 0; i < 4; i++) {
            *(uint4*)(g_hT_hi + base + i * 8) = make_uint4(hw[i*4], hw[i*4+1], hw[i*4+2], hw[i*4+3]);
            *(uint4*)(g_hT_lo + base + i * 8) = make_uint4(lw[i*4], lw[i*4+1], lw[i*4+2], lw[i*4+3]);
        }
    }
}

// ---------------- 3) tensor-core fused attention (mma.sync bf16x3) ----------
// P (A-operand) fragments built DIRECTLY in registers — no STS/LDSM for P.
// Each lane computes the 8 P values of its m16n8k16 A fragment per kc:
//   rows r0 = warp*16 + (lane>>2), r1 = r0+8; k = (lane&3)*2 {+0,+1,+8,+9}.
// B (h^T) tiles double-buffered in SMEM. Row sums via ones-MMA.
#define BUF_SZ    16384      // BH 8K + BL 8K
#define BH_R      0
#define BL_R      8192
#define F2P_OFF   32768      // 512 float2 = 4KB
#define SMEM_ATTN 37376
#define WOUT_OFF  33280      // epilogue Wout slice after hstage (128*65*4)

__global__ __launch_bounds__(256, 2) void k_attn(const float* __restrict__ Wout) {
    extern __shared__ char sm[];
    uint32_t smb = smem_u32(sm);
    float2* f2p = (float2*)(sm + F2P_OFF);
    int head = blockIdx.z, b = blockIdx.y, n0 = blockIdx.x * 128;
    int hb = head * BB + b;
    int tid = threadIdx.x, warp = tid >> 5, lane = tid & 31;

    // factorized-exp tables
    #pragma unroll
    for (int i = 0; i < 2; i++) {
        int m = tid + i * 256;
        float f2v = g_f2[hb * NN + m];
        f2p[m] = make_float2(__expf(f2v), __expf(ALPHA * f2v));
    }

    // per-lane fragment row constants
    int g = lane >> 2, t4 = lane & 3;
    int r0 = warp * 16 + g;                  // fragment row (local)
    float f1a = g_f1[hb * NN + n0 + r0];
    float f1b = g_f1[hb * NN + n0 + r0 + 8];
    float Ae0 = __expf(f1a), A2e0 = __expf(ALPHA * f1a);
    float Ae1 = __expf(f1b), A2e1 = __expf(ALPHA * f1b);
    const uint2* adjr0 = (const uint2*)(g_adjb + (size_t)(b * NN + n0 + r0) * 16);
    const uint2* adjr1 = (const uint2*)(g_adjb + (size_t)(b * NN + n0 + r0 + 8) * 16);

    float c[8][4];
    #pragma unroll
    for (int i = 0; i < 8; i++)
        #pragma unroll
        for (int j = 0; j < 4; j++) c[i][j] = 0.f;
    float c2[4] = {0.f, 0.f, 0.f, 0.f};     // ones-MMA row sums

    int q = lane >> 3, ri = lane & 7;
    int frow = ((q & 1) << 3) + ri;
    int akb  = (q >> 1) << 4;

    // hoisted B LDSM addresses (buffer-relative)
    uint32_t boff[4][4];
    #pragma unroll
    for (int kc = 0; kc < 4; kc++)
        #pragma unroll
        for (int np = 0; np < 4; np++)
            boff[np][kc] = SWZ((np * 16 + frow) * 128 + kc * 32 + akb);

    const uint4* shp = (const uint4*)g_hT_hi + (size_t)hb * FH * (NN / 8);
    const uint4* slp = (const uint4*)g_hT_lo + (size_t)hb * FH * (NN / 8);

    // B-tile producer geometry
    int bf = tid >> 3, bj = tid & 7;
    uint32_t bso  = SWZ(bf * 128 + bj * 16);
    uint32_t bso1 = SWZ((bf + 32) * 128 + bj * 16);
    int bgi0 = bf * 64 + bj, bgi1 = (bf + 32) * 64 + bj;

    #define PRODUCE_B(chv, bufbase) { \
        *(uint4*)(sm + (bufbase) + BH_R + bso)  = shp[bgi0 + (chv) * 8]; \
        *(uint4*)(sm + (bufbase) + BH_R + bso1) = shp[bgi1 + (chv) * 8]; \
        *(uint4*)(sm + (bufbase) + BL_R + bso)  = slp[bgi0 + (chv) * 8]; \
        *(uint4*)(sm + (bufbase) + BL_R + bso1) = slp[bgi1 + (chv) * 8]; \
    }

    PRODUCE_B(0, 0)
    __syncthreads();                          // f2p + buf0 visible

    for (int ch = 0; ch < 8; ch++) {
        uint32_t bufb = (ch & 1) * BUF_SZ;
        // 64-bit adjacency words for this chunk, both fragment rows
        uint2 w0 = adjr0[ch], w1 = adjr1[ch];
        unsigned long long M0 = ((unsigned long long)w0.y << 32) | w0.x;
        unsigned long long M1 = ((unsigned long long)w1.y << 32) | w1.x;
        const float2* f2c = f2p + ch * 64;

        #pragma unroll
        for (int kc = 0; kc < 4; kc++) {
            int mk = kc * 16 + t4 * 2;        // within-chunk m of this lane's frag
            float4 tA = *(const float4*)(f2c + mk);       // m = mk, mk+1
            float4 tB = *(const float4*)(f2c + mk + 8);   // m = mk+8, mk+9
            // 8 P values of the A fragment
            float p00 = ((M0 >> mk) & 1)       ? fmaxf(Ae0 * tA.x, A2e0 * tA.y) : 0.f;
            float p01 = ((M0 >> (mk + 1)) & 1) ? fmaxf(Ae0 * tA.z, A2e0 * tA.w) : 0.f;
            float p10 = ((M1 >> mk) & 1)       ? fmaxf(Ae1 * tA.x, A2e1 * tA.y) : 0.f;
            float p11 = ((M1 >> (mk + 1)) & 1) ? fmaxf(Ae1 * tA.z, A2e1 * tA.w) : 0.f;
            float p02 = ((M0 >> (mk + 8)) & 1) ? fmaxf(Ae0 * tB.x, A2e0 * tB.y) : 0.f;
            float p03 = ((M0 >> (mk + 9)) & 1) ? fmaxf(Ae0 * tB.z, A2e0 * tB.w) : 0.f;
            float p12 = ((M1 >> (mk + 8)) & 1) ? fmaxf(Ae1 * tB.x, A2e1 * tB.y) : 0.f;
            float p13 = ((M1 >> (mk + 9)) & 1) ? fmaxf(Ae1 * tB.z, A2e1 * tB.w) : 0.f;
            uint32_t ah[4], al[4];
            split2t(p00, p01, ah[0], al[0]);
            split2t(p10, p11, ah[1], al[1]);
            split2t(p02, p03, ah[2], al[2]);
            split2t(p12, p13, ah[3], al[3]);
            // row sums
            MMA16816(c2, ah[0], ah[1], ah[2], ah[3], ONES2, ONES2);
            MMA16816(c2, al[0], al[1], al[2], al[3], ONES2, ONES2);
            #pragma unroll
            for (int np = 0; np < 4; np++) {
                uint32_t bh[4], bl[4];
                LDSM_X4(bh[0], bh[1], bh[2], bh[3], smb + bufb + BH_R + boff[np][kc]);
                LDSM_X4(bl[0], bl[1], bl[2], bl[3], smb + bufb + BL_R + boff[np][kc]);
                MMA16816(c[np*2],   ah[0], ah[1], ah[2], ah[3], bh[0], bh[2]);
                MMA16816(c[np*2],   ah[0], ah[1], ah[2], ah[3], bl[0], bl[2]);
                MMA16816(c[np*2],   al[0], al[1], al[2], al[3], bh[0], bh[2]);
                MMA16816(c[np*2+1], ah[0], ah[1], ah[2], ah[3], bh[1], bh[3]);
                MMA16816(c[np*2+1], ah[0], ah[1], ah[2], ah[3], bl[1], bl[3]);
                MMA16816(c[np*2+1], al[0], al[1], al[2], al[3], bh[1], bh[3]);
            }
        }
        if (ch < 7) PRODUCE_B(ch + 1, (uint32_t)(((ch + 1) & 1) * BUF_SZ))
        __syncthreads();
    }

    // rinv straight from ones-MMA accumulators (all cols of a row identical)
    float rinv0 = 1.0f / c2[0];
    float rinv1 = 1.0f / c2[2];

    // ---- stage elu(h'/s) [128][65] fp32 + load Wout slice ----
    float* hstage = (float*)sm;
    float* swout  = (float*)(sm + WOUT_OFF);
    ((float4*)swout)[tid] = ((const float4*)Wout)[head * 256 + tid];
    int row0e = warp * 16 + g;
    #pragma unroll
    for (int np = 0; np < 8; np++) {
        int col = np * 8 + t4 * 2;
        float u0 = c[np][0] * rinv0, u1 = c[np][1] * rinv0;
        float v0 = c[np][2] * rinv1, v1 = c[np][3] * rinv1;
        u0 = u0 > 0.f ? u0 : expm1f(u0);
        u1 = u1 > 0.f ? u1 : expm1f(u1);
        v0 = v0 > 0.f ? v0 : expm1f(v0);
        v1 = v1 > 0.f ? v1 : expm1f(v1);
        hstage[row0e * 65 + col]         = u0;
        hstage[row0e * 65 + col + 1]     = u1;
        hstage[(row0e + 8) * 65 + col]   = v0;
        hstage[(row0e + 8) * 65 + col+1] = v1;
    }
    __syncthreads();

    // ---- partial hout ----
    {
        int row = tid >> 1, chf = tid & 1;
        float acc[8] = {};
        #pragma unroll 8
        for (int k = 0; k < 64; k++) {
            float a = hstage[row * 65 + k];
            const float* wr = swout + k * 16 + chf * 8;
            #pragma unroll
            for (int j = 0; j < 8; j++) acc[j] = fmaf(a, wr[j], acc[j]);
        }
        float* op = g_houtp + ((size_t)head * BB * NN + b * NN + n0 + row) * NC + chf * 8;
        *(float4*)op       = make_float4(acc[0], acc[1], acc[2], acc[3]);
        *(float4*)(op + 4) = make_float4(acc[4], acc[5], acc[6], acc[7]);
    }
}

// ---------------- 4) combine partial hout + f1o/f2o -------------------------
__global__ __launch_bounds__(256) void k_combine(const float* __restrict__ a1o,
                                                 const float* __restrict__ a2o) {
    int bn = blockIdx.x * 256 + threadIdx.x;
    float acc[16] = {};
    #pragma unroll
    for (int h = 0; h < NH; h++) {
        const float4* p = (const float4*)(g_houtp + ((size_t)h * BB * NN + bn) * NC);
        #pragma unroll
        for (int i = 0; i < 4; i++) {
            float4 v = p[i];
            acc[i*4]   += v.x; acc[i*4+1] += v.y;
            acc[i*4+2] += v.z; acc[i*4+3] += v.w;
        }
    }
    float4* op = (float4*)(g_hout + (size_t)bn * NC);
    #pragma unroll
    for (int i = 0; i < 4; i++)
        op[i] = make_float4(acc[i*4], acc[i*4+1], acc[i*4+2], acc[i*4+3]);
    float s1 = 0.f, s2 = 0.f;
    #pragma unroll
    for (int c = 0; c < 16; c++) { s1 = fmaf(acc[c], a1o[c], s1); s2 = fmaf(acc[c], a2o[c], s2); }
    g_f1o[bn] = s1; g_f2o[bn] = s2;
}

// ---------------- 5) output attention (F=16, max-factorized exp) ------------
__global__ __launch_bounds__(256) void k_attn_out(float* __restrict__ out) {
    int b = blockIdx.y, n0 = blockIdx.x * 64;
    __shared__ float2   f2p[NN];        // 4KB
    __shared__ unsigned adjw[64 * 16];  // 4KB
    __shared__ float    hs[64 * 16];    // 4KB
    __shared__ float    ps[64 * 68];    // 17.4KB
    int tid = threadIdx.x;

    #pragma unroll
    for (int i = 0; i < 2; i++) {
        int m = tid + i * 256;
        float f2v = g_f2o[b * NN + m];
        f2p[m] = make_float2(__expf(f2v), __expf(ALPHA * f2v));
    }
    {
        const unsigned* ab = g_adjb + (size_t)(b * NN + n0) * 16;
        for (int i = tid; i < 1024; i += 256) adjw[i] = ab[i];
    }
    int r = tid >> 2, q = tid & 3;
    float f1v = g_f1o[b * NN + n0 + r];
    float Ae = __expf(f1v), A2e = __expf(ALPHA * f1v);

    float s = 0.f;
    float4 acc = {0, 0, 0, 0};
    const float4* hg4 = (const float4*)g_hout + (size_t)b * NN * 4;
    for (int c = 0; c < 8; c++) {
        __syncthreads();
        ((float4*)hs)[tid] = hg4[c * 256 + tid];
        {
            unsigned word = adjw[(r << 4) + c * 2 + (q >> 1)];
            int sb = (q & 1) * 16;
            const float2* bp = f2p + c * 64 + q * 16;
            #pragma unroll
            for (int t = 0; t < 16; t++) {
                float2 Bv = bp[t];
                float val = fmaxf(Ae * Bv.x, A2e * Bv.y);
                val = ((word >> (sb + t)) & 1u) ? val : 0.f;
                ps[r * 68 + q * 16 + t] = val;
            }
        }
        __syncthreads();
        #pragma unroll 8
        for (int mm = 0; mm < 64; mm++) {
            float p = ps[r * 68 + mm];
            s += p;
            float4 hv = ((const float4*)hs)[mm * 4 + q];
            acc.x = fmaf(p, hv.x, acc.x); acc.y = fmaf(p, hv.y, acc.y);
            acc.z = fmaf(p, hv.z, acc.z); acc.w = fmaf(p, hv.w, acc.w);
        }
    }
    float rinv = 1.0f / s;
    acc.x *= rinv; acc.y *= rinv; acc.z *= rinv; acc.w *= rinv;
    *(float4*)&out[(size_t)(b * NN + n0 + r) * NC + (q << 2)] = acc;
}

// ---------------- launch ----------------------------------------------------
extern "C" void kernel_launch(void* const* d_in, const int* in_sizes, int n_in,
                              void* d_out, int out_size) {
    const float* x   = (const float*)d_in[0];
    const int*   adj = (const int*)  d_in[1];
    const float* Wh  = (const float*)d_in[2];
    const float* a1h = (const float*)d_in[3];
    const float* a2h = (const float*)d_in[4];
    const float* Wo  = (const float*)d_in[5];
    const float* a1o = (const float*)d_in[6];
    const float* a2o = (const float*)d_in[7];
    float* out = (float*)d_out;

    cudaFuncSetAttribute(k_head_gemm, cudaFuncAttributeMaxDynamicSharedMemorySize, SMEM_HG);
    cudaFuncSetAttribute(k_attn, cudaFuncAttributeMaxDynamicSharedMemorySize, SMEM_ATTN);

    k_pack_adj <<<BB * NN * 16 / 8, 256>>>(adj);
    k_prep     <<<2112, 256>>>(x, Wh);
    k_head_gemm<<<dim3(8, BB, NH), 128, SMEM_HG>>>(a1h, a2h);
    k_attn     <<<dim3(4, BB, NH), 256, SMEM_ATTN>>>(Wo);
    k_combine  <<<BB * NN / 256, 256>>>(a1o, a2o);
    k_attn_out <<<dim3(8, BB), 256>>>(out);
}